// round 16
// baseline (speedup 1.0000x reference)
#include <cuda_runtime.h>
#include <cuda_bf16.h>
#include <math.h>
#include <stdint.h>

#define Nn 10000
#define Ee 160000
#define EPE 170000      // E + N self loops
#define Dd 128
#define HC 512
#define ASTRIDE 136     // padded bf16 row stride for 128-wide k tiles (gemm2)
#define KSTRIDE 72      // padded bf16 row stride for 64-wide k tiles (gemm1)

typedef unsigned long long u64;

// ---- channel permutation: storage pos p <-> logical channel c -------------
// c = 128g + 16i + 4q + j ;  p = q*128 + g*32 + i*4 + j
__device__ __forceinline__ int chOf(int p) {
    int q = p >> 7, r = p & 127, g = r >> 5, w = r & 31, i = w >> 2, j = w & 3;
    return 128 * g + 16 * i + 4 * q + j;
}

// ---------------- smem helpers ----------------
__device__ __forceinline__ uint32_t saddr(const void* p) {
    return (uint32_t)__cvta_generic_to_shared(p);
}

// ---------------- packed f32x2 helpers ----------------
__device__ __forceinline__ u64 pk2(float lo, float hi) {
    u64 r; asm("mov.b64 %0, {%1, %2};" : "=l"(r) : "f"(lo), "f"(hi)); return r;
}
__device__ __forceinline__ void upk2(u64 v, float& lo, float& hi) {
    asm("mov.b64 {%0, %1}, %2;" : "=f"(lo), "=f"(hi) : "l"(v));
}
__device__ __forceinline__ void fma2(u64& d, u64 a, u64 b) {
    asm("fma.rn.f32x2 %0, %1, %2, %0;" : "+l"(d) : "l"(a), "l"(b));
}
__device__ __forceinline__ u64 add2(u64 a, u64 b) {
    u64 r; asm("add.rn.f32x2 %0, %1, %2;" : "=l"(r) : "l"(a), "l"(b)); return r;
}
__device__ __forceinline__ u64 mul2(u64 a, u64 b) {
    u64 r; asm("mul.rn.f32x2 %0, %1, %2;" : "=l"(r) : "l"(a), "l"(b)); return r;
}

// ---------------- mma.sync helpers ----------------
__device__ __forceinline__ void ldsm4(uint32_t* r, uint32_t addr) {
    asm volatile("ldmatrix.sync.aligned.m8n8.x4.shared.b16 {%0,%1,%2,%3}, [%4];"
        : "=r"(r[0]), "=r"(r[1]), "=r"(r[2]), "=r"(r[3]) : "r"(addr));
}
__device__ __forceinline__ void mma16816(float* c, const uint32_t* a, uint32_t b0, uint32_t b1) {
    asm volatile(
        "mma.sync.aligned.m16n8k16.row.col.f32.bf16.bf16.f32 "
        "{%0,%1,%2,%3}, {%4,%5,%6,%7}, {%8,%9}, {%0,%1,%2,%3};"
        : "+f"(c[0]), "+f"(c[1]), "+f"(c[2]), "+f"(c[3])
        : "r"(a[0]), "r"(a[1]), "r"(a[2]), "r"(a[3]), "r"(b0), "r"(b1));
}

// ---------------- device scratch ----------------
__device__ float g_xl[Nn * HC];                 // PERMUTED columns
__device__ float g_xr[Nn * HC];                 // PERMUTED columns
__device__ __nv_bfloat16 g_agghi[Nn * HC];      // PERMUTED columns
__device__ __nv_bfloat16 g_agglo[Nn * HC];
__device__ int   g_deg[Nn];
__device__ int   g_off[Nn + 1];
__device__ int   g_cur[Nn];
__device__ int   g_esrc[EPE];
__device__ float g_eav[EPE];
__device__ float g_easum;
__device__ __nv_bfloat16 g_xhi[Nn * Dd];
__device__ __nv_bfloat16 g_xlo[Nn * Dd];
__device__ __nv_bfloat16 g_wthi[2 * HC * Dd];   // [mat][n][k] = W[k][n]
__device__ __nv_bfloat16 g_wtlo[2 * HC * Dd];
__device__ __nv_bfloat16 g_wphi[Dd * HC];       // [n=128][k_perm=512]
__device__ __nv_bfloat16 g_wplo[Dd * HC];

// ---------------- init ----------------
__global__ void k_init() {
    int i = blockIdx.x * blockDim.x + threadIdx.x;
    if (i < Nn) { g_deg[i] = 0; g_cur[i] = 0; }
    if (i == 0) g_easum = 0.f;
}

// ---------------- convert x -> bf16 hi/lo ----------------
__global__ void k_cvt_x(const float* __restrict__ x) {
    int i = blockIdx.x * 256 + threadIdx.x;
    if (i >= Nn * Dd / 2) return;
    float2 v = ((const float2*)x)[i];
    __nv_bfloat16 h0 = __float2bfloat16(v.x), h1 = __float2bfloat16(v.y);
    __nv_bfloat16 l0 = __float2bfloat16(v.x - __bfloat162float(h0));
    __nv_bfloat16 l1 = __float2bfloat16(v.y - __bfloat162float(h1));
    ((__nv_bfloat162*)g_xhi)[i] = __halves2bfloat162(h0, h1);
    ((__nv_bfloat162*)g_xlo)[i] = __halves2bfloat162(l0, l1);
}

// ---------------- transpose+convert Wl/Wr -> [n][k] bf16 hi/lo -------------
__global__ void k_cvt_w(const float* __restrict__ Wl, const float* __restrict__ Wr) {
    __shared__ float t[32][33];
    int m = blockIdx.z;
    const float* W = m ? Wr : Wl;
    int nb = blockIdx.x * 32, kb = blockIdx.y * 32;
    int tx = threadIdx.x, ty = threadIdx.y;
#pragma unroll
    for (int j = 0; j < 4; j++)
        t[ty + 8 * j][tx] = W[(kb + ty + 8 * j) * HC + nb + tx];
    __syncthreads();
#pragma unroll
    for (int j = 0; j < 4; j++) {
        float v = t[tx][ty + 8 * j];
        __nv_bfloat16 h = __float2bfloat16(v);
        __nv_bfloat16 l = __float2bfloat16(v - __bfloat162float(h));
        int o = m * HC * Dd + (nb + ty + 8 * j) * Dd + kb + tx;
        g_wthi[o] = h;
        g_wtlo[o] = l;
    }
}

// ---------------- Wp -> [n][k_perm] bf16 hi/lo (gather permutation) --------
__global__ void k_cvt_wp(const float* __restrict__ Wp) {
    int idx = blockIdx.x * 256 + threadIdx.x;
    if (idx >= Dd * HC) return;
    int n = idx >> 9, p = idx & 511;
    float v = Wp[(size_t)chOf(p) * Dd + n];
    __nv_bfloat16 h = __float2bfloat16(v);
    __nv_bfloat16 l = __float2bfloat16(v - __bfloat162float(h));
    g_wphi[(size_t)n * HC + p] = h;
    g_wplo[(size_t)n * HC + p] = l;
}

// ---------------- GEMM1: mma.sync bf16, K split into 2 stages of 64 --------
// smem 73728 B + launch_bounds(256,2) -> 2 CTAs/SM (fill/compute overlap).
#define SMEM_G1 (4 * 128 * KSTRIDE * 2)   // 73728 B ; Csm 128*132*4=67584 fits
#define CSTRIDE 132

__global__ __launch_bounds__(256, 2) void k_gemm1_mma(const float* __restrict__ bl,
                                                      const float* __restrict__ br) {
    extern __shared__ __nv_bfloat16 smb[];
    __nv_bfloat16* Ah = smb;
    __nv_bfloat16* Al = Ah + 128 * KSTRIDE;
    __nv_bfloat16* Bh = Al + 128 * KSTRIDE;
    __nv_bfloat16* Bl = Bh + 128 * KSTRIDE;
    float* Csm = (float*)smb;                    // reused after compute

    int tid = threadIdx.x, wid = tid >> 5, lane = tid & 31;
    int cb = blockIdx.y;
    int mat = cb >> 2, g = cb & 3, colbase = g * 128;
    const float* bias = mat ? br : bl;
    float* out = mat ? g_xr : g_xl;
    int row0 = blockIdx.x * 128;

    const __nv_bfloat16* gbh = g_wthi + (size_t)mat * HC * Dd + (size_t)colbase * Dd;
    const __nv_bfloat16* gbl = g_wtlo + (size_t)mat * HC * Dd + (size_t)colbase * Dd;

    float acc[4][4][4];
#pragma unroll
    for (int mt = 0; mt < 4; mt++)
#pragma unroll
        for (int nt = 0; nt < 4; nt++)
#pragma unroll
            for (int j = 0; j < 4; j++) acc[mt][nt][j] = 0.f;

    int warpM = wid & 1, warpN = wid >> 1;
    int mbase = warpM * 64, nbase = warpN * 32;
    int t8 = lane >> 3, r8 = lane & 7;
    int aRow = (t8 & 1) * 8 + r8, aK = (t8 >> 1) * 8;
    int bN = (t8 >> 1) * 8 + r8, bK = (t8 & 1) * 8;

#pragma unroll 1
    for (int stage = 0; stage < 2; stage++) {
        int k0 = stage * 64;
        // fill: per array 128 rows x 8 uint4 chunks = 1024, 4/thread
#pragma unroll
        for (int i = 0; i < 4; i++) {
            int idx = tid + i * 256;
            int row = idx >> 3, ch = idx & 7;
            int grow = row0 + row;
            uint4 vh = make_uint4(0, 0, 0, 0), vl = make_uint4(0, 0, 0, 0);
            if (grow < Nn) {
                vh = *(const uint4*)(g_xhi + (size_t)grow * Dd + k0 + ch * 8);
                vl = *(const uint4*)(g_xlo + (size_t)grow * Dd + k0 + ch * 8);
            }
            *(uint4*)(Ah + row * KSTRIDE + ch * 8) = vh;
            *(uint4*)(Al + row * KSTRIDE + ch * 8) = vl;
            *(uint4*)(Bh + row * KSTRIDE + ch * 8) = *(const uint4*)(gbh + row * Dd + k0 + ch * 8);
            *(uint4*)(Bl + row * KSTRIDE + ch * 8) = *(const uint4*)(gbl + row * Dd + k0 + ch * 8);
        }
        __syncthreads();

#pragma unroll
        for (int term = 0; term < 3; term++) {
            const __nv_bfloat16* Asm = (term == 2) ? Al : Ah;
            const __nv_bfloat16* Bsm = (term == 1) ? Bl : Bh;
#pragma unroll
            for (int ks = 0; ks < 4; ks++) {
                uint32_t a[4][4], b[2][4];
#pragma unroll
                for (int mt = 0; mt < 4; mt++)
                    ldsm4(a[mt], saddr(Asm + (mbase + mt * 16 + aRow) * KSTRIDE + ks * 16 + aK));
#pragma unroll
                for (int gg = 0; gg < 2; gg++)
                    ldsm4(b[gg], saddr(Bsm + (nbase + gg * 16 + bN) * KSTRIDE + ks * 16 + bK));
#pragma unroll
                for (int mt = 0; mt < 4; mt++)
#pragma unroll
                    for (int nt = 0; nt < 4; nt++)
                        mma16816(acc[mt][nt], a[mt],
                                 b[nt >> 1][(nt & 1) * 2], b[nt >> 1][(nt & 1) * 2 + 1]);
            }
        }
        __syncthreads();
    }

    // stage C (+bias) into smem in LOCAL permuted order:
    int rA = lane >> 2, cA = 2 * (lane & 3);
#pragma unroll
    for (int nt = 0; nt < 4; nt++) {
        int c = nbase + nt * 8 + cA;
        float2 bv = *(const float2*)(bias + colbase + c);
        int ploc = ((c & 15) >> 2) * 32 + (c >> 4) * 4 + (c & 3);
#pragma unroll
        for (int mt = 0; mt < 4; mt++) {
            int row = mbase + mt * 16 + rA;
            *(float2*)&Csm[row * CSTRIDE + ploc] =
                make_float2(acc[mt][nt][0] + bv.x, acc[mt][nt][1] + bv.y);
            *(float2*)&Csm[(row + 8) * CSTRIDE + ploc] =
                make_float2(acc[mt][nt][2] + bv.x, acc[mt][nt][3] + bv.y);
        }
    }
    __syncthreads();

    // coalesced permuted global stores: ploc = q*32 + w -> p = q*128 + g*32 + w
#pragma unroll
    for (int it = 0; it < 16; it++) {
        int idx = tid + it * 256;
        int row = idx >> 5, t = idx & 31;
        int grow = row0 + row;
        if (grow < Nn) {
            float4 v = *(float4*)&Csm[row * CSTRIDE + t * 4];
            int p = (t >> 3) * 128 + g * 32 + (t & 7) * 4;
            *(float4*)(out + (size_t)grow * HC + p) = v;
        }
    }
}

// ---------------- degree histogram + edge_attr sum (fused) ----------------
__global__ void k_degree(const int* __restrict__ ei, const float* __restrict__ ea) {
    __shared__ float sh[8];
    int e = blockIdx.x * blockDim.x + threadIdx.x;
    float v = 0.f;
    if (e < EPE) {
        int dst = (e < Ee) ? ei[Ee + e] : (e - Ee);
        atomicAdd(&g_deg[dst], 1);
        if (e < Ee) v = ea[e];
    }
#pragma unroll
    for (int o = 16; o; o >>= 1) v += __shfl_xor_sync(0xffffffffu, v, o);
    if ((threadIdx.x & 31) == 0) sh[threadIdx.x >> 5] = v;
    __syncthreads();
    if (threadIdx.x == 0) {
        float s = 0.f;
#pragma unroll
        for (int w = 0; w < 8; w++) s += sh[w];
        atomicAdd(&g_easum, s);
    }
}

// ---------------- exclusive scan over N (single block) ----------------
__global__ void k_scan() {
    __shared__ int sb[1024];
    int t = threadIdx.x;
    const int CH = 10;
    int lo = t * CH;
    int s = 0;
    for (int i = 0; i < CH; i++) { int idx = lo + i; if (idx < Nn) s += g_deg[idx]; }
    sb[t] = s;
    __syncthreads();
    for (int o = 1; o < 1024; o <<= 1) {
        int v = (t >= o) ? sb[t - o] : 0;
        __syncthreads();
        sb[t] += v;
        __syncthreads();
    }
    int run = sb[t] - s;
    for (int i = 0; i < CH; i++) {
        int idx = lo + i;
        if (idx < Nn) { g_off[idx] = run; run += g_deg[idx]; }
    }
    if (t == 1023) g_off[Nn] = sb[1023];
}

// ---------------- scatter edges into CSR by dst ----------------
__global__ void k_scatter(const int* __restrict__ ei, const float* __restrict__ ea) {
    int e = blockIdx.x * blockDim.x + threadIdx.x;
    if (e >= EPE) return;
    int src, dst; float a;
    if (e < Ee) { src = ei[e]; dst = ei[Ee + e]; a = ea[e]; }
    else        { src = e - Ee; dst = src; a = g_easum * (1.0f / Ee); }
    int pos = atomicAdd(&g_cur[dst], 1);
    int idx = g_off[dst] + pos;
    g_esrc[idx] = src;
    g_eav[idx]  = a;
}

// ---------------- warp-per-node aggregation, packed f32x2 math -------------
// leaky(z) = max(z, 0.2z) = 0.6z + 0.4|z|  (exact to ulp, branch-free packed)
__global__ __launch_bounds__(256) void k_aggregate(const float* __restrict__ We,
        const float* __restrict__ att, const float* __restrict__ bias_out) {
    __shared__ float s_we[HC], s_at[HC];
    for (int p = threadIdx.x; p < HC; p += 256) {
        int ch = chOf(p);
        s_we[p] = We[ch];
        s_at[p] = att[ch];
    }
    __syncthreads();

    int gw = (blockIdx.x * 256 + threadIdx.x) >> 5;
    if (gw >= Nn) return;
    int lane = threadIdx.x & 31;
    int co = lane * 4;
    int g = lane >> 3, i = lane & 7;

    const u64 MASK = 0x7FFFFFFF7FFFFFFFull;
    const u64 C04 = pk2(0.4f, 0.4f), C06 = pk2(0.6f, 0.6f);

    u64 xr2[8], we2[8], at2[8], acc2[8];
#pragma unroll
    for (int q = 0; q < 4; q++) {
        float4 v = *(const float4*)(g_xr + (size_t)gw * HC + q * 128 + co);
        xr2[q*2] = pk2(v.x, v.y); xr2[q*2+1] = pk2(v.z, v.w);
        float4 w4 = *(const float4*)&s_we[q * 128 + co];
        we2[q*2] = pk2(w4.x, w4.y); we2[q*2+1] = pk2(w4.z, w4.w);
        float4 a4 = *(const float4*)&s_at[q * 128 + co];
        at2[q*2] = pk2(a4.x, a4.y); at2[q*2+1] = pk2(a4.z, a4.w);
    }
#pragma unroll
    for (int k = 0; k < 8; k++) acc2[k] = 0ull;

    float ssum = 0.f;
    int e0 = g_off[gw], e1 = g_off[gw + 1];

    u64 bufA[8], bufB[8];
    auto ldxv = [&](u64* d, int s) {
#pragma unroll
        for (int q = 0; q < 4; q++) {
            ulonglong2 v = *(const ulonglong2*)(g_xl + (size_t)s * HC + q * 128 + co);
            d[q*2] = v.x; d[q*2+1] = v.y;
        }
    };
    auto process = [&](const u64* xv, float a) {
        u64 a2 = pk2(a, a);
        u64 pp = 0ull;
#pragma unroll
        for (int k = 0; k < 8; k++) {
            u64 t = xr2[k];
            fma2(t, a2, we2[k]);          // t = xr + a*we
            u64 z = add2(t, xv[k]);       // z = xv + xr + a*we
            u64 r = mul2(z & MASK, C04);  // 0.4|z|
            fma2(r, z, C06);              // 0.6z + 0.4|z| = leaky(z)
            fma2(pp, r, at2[k]);          // dot with att
        }
        float plo, phi;
        upk2(pp, plo, phi);
        float p = plo + phi;
        p += __shfl_xor_sync(0xffffffffu, p, 1);
        p += __shfl_xor_sync(0xffffffffu, p, 2);
        p += __shfl_xor_sync(0xffffffffu, p, 4);
        float w = __expf(p);
        ssum += w;
        u64 w2 = pk2(w, w);
#pragma unroll
        for (int k = 0; k < 8; k++) fma2(acc2[k], w2, xv[k]);
    };

    if (e0 < e1) {
        ldxv(bufA, g_esrc[e0]);
        int e = e0;
        for (; e + 2 <= e1; e += 2) {
            ldxv(bufB, g_esrc[e + 1]);
            process(bufA, g_eav[e]);
            if (e + 2 < e1) ldxv(bufA, g_esrc[e + 2]);
            process(bufB, g_eav[e + 1]);
        }
        if (e < e1) process(bufA, g_eav[e]);
    }

    float inv = 1.f / (ssum + 1e-16f);
#pragma unroll
    for (int q = 0; q < 4; q++) {
        float4 bo = *(const float4*)(bias_out + g * 128 + i * 16 + q * 4);
        float a0, a1, a2v, a3;
        upk2(acc2[q*2], a0, a1);
        upk2(acc2[q*2+1], a2v, a3);
        float v0 = fmaf(a0, inv, bo.x);
        float v1 = fmaf(a1, inv, bo.y);
        float v2 = fmaf(a2v, inv, bo.z);
        float v3 = fmaf(a3, inv, bo.w);
        __nv_bfloat16 h0 = __float2bfloat16(v0), h1 = __float2bfloat16(v1);
        __nv_bfloat16 h2 = __float2bfloat16(v2), h3 = __float2bfloat16(v3);
        __nv_bfloat16 l0 = __float2bfloat16(v0 - __bfloat162float(h0));
        __nv_bfloat16 l1 = __float2bfloat16(v1 - __bfloat162float(h1));
        __nv_bfloat16 l2 = __float2bfloat16(v2 - __bfloat162float(h2));
        __nv_bfloat16 l3 = __float2bfloat16(v3 - __bfloat162float(h3));
        size_t o = (size_t)gw * HC + q * 128 + co;
        *(__nv_bfloat162*)(g_agghi + o)     = __halves2bfloat162(h0, h1);
        *(__nv_bfloat162*)(g_agghi + o + 2) = __halves2bfloat162(h2, h3);
        *(__nv_bfloat162*)(g_agglo + o)     = __halves2bfloat162(l0, l1);
        *(__nv_bfloat162*)(g_agglo + o + 2) = __halves2bfloat162(l2, l3);
    }
}

// ---------------- GEMM2 via mma.sync + GELU/LN epilogue ---------------------
#define SMEM_G2 ((64 * ASTRIDE * 2 + 128 * ASTRIDE * 2) * 2)   // 104448 B

__global__ __launch_bounds__(256) void k_gemm2_mma(const float* __restrict__ x,
        const float* __restrict__ bp, const float* __restrict__ gamma,
        const float* __restrict__ beta, float* __restrict__ out) {
    extern __shared__ __nv_bfloat16 smb2[];
    __nv_bfloat16* Ah = smb2;
    __nv_bfloat16* Al = Ah + 64 * ASTRIDE;
    __nv_bfloat16* Bh = Al + 64 * ASTRIDE;
    __nv_bfloat16* Bl = Bh + 128 * ASTRIDE;
    float* Csm = (float*)smb2;

    int tid = threadIdx.x, wid = tid >> 5, lane = tid & 31;
    int row0 = blockIdx.x * 64;

    float acc[2][4][4];
#pragma unroll
    for (int mt = 0; mt < 2; mt++)
#pragma unroll
        for (int nt = 0; nt < 4; nt++)
#pragma unroll
            for (int j = 0; j < 4; j++) acc[mt][nt][j] = 0.f;

    int warpM = wid & 1, warpN = wid >> 1;
    int mbase = warpM * 32, nbase = warpN * 32;
    int t8 = lane >> 3, r8 = lane & 7;
    int aRow = (t8 & 1) * 8 + r8, aK = (t8 >> 1) * 8;
    int bN = (t8 >> 1) * 8 + r8, bK = (t8 & 1) * 8;

#pragma unroll 1
    for (int stage = 0; stage < 4; stage++) {
        int k0 = stage * 128;
#pragma unroll
        for (int i = 0; i < 4; i++) {
            int idx = tid + i * 256;
            int row = idx >> 4, ch = idx & 15;
            int grow = row0 + row;
            uint4 vh = make_uint4(0, 0, 0, 0), vl = make_uint4(0, 0, 0, 0);
            if (grow < Nn) {
                vh = *(const uint4*)(g_agghi + (size_t)grow * HC + k0 + ch * 8);
                vl = *(const uint4*)(g_agglo + (size_t)grow * HC + k0 + ch * 8);
            }
            *(uint4*)(Ah + row * ASTRIDE + ch * 8) = vh;
            *(uint4*)(Al + row * ASTRIDE + ch * 8) = vl;
        }
#pragma unroll
        for (int i = 0; i < 8; i++) {
            int idx = tid + i * 256;
            int row = idx >> 4, ch = idx & 15;
            *(uint4*)(Bh + row * ASTRIDE + ch * 8) =
                *(const uint4*)(g_wphi + (size_t)row * HC + k0 + ch * 8);
            *(uint4*)(Bl + row * ASTRIDE + ch * 8) =
                *(const uint4*)(g_wplo + (size_t)row * HC + k0 + ch * 8);
        }
        __syncthreads();

#pragma unroll
        for (int term = 0; term < 3; term++) {
            const __nv_bfloat16* Asm = (term == 2) ? Al : Ah;
            const __nv_bfloat16* Bsm = (term == 1) ? Bl : Bh;
#pragma unroll
            for (int ks = 0; ks < 8; ks++) {
                uint32_t a[2][4], b[2][4];
#pragma unroll
                for (int mt = 0; mt < 2; mt++)
                    ldsm4(a[mt], saddr(Asm + (mbase + mt * 16 + aRow) * ASTRIDE + ks * 16 + aK));
#pragma unroll
                for (int gg = 0; gg < 2; gg++)
                    ldsm4(b[gg], saddr(Bsm + (nbase + gg * 16 + bN) * ASTRIDE + ks * 16 + bK));
#pragma unroll
                for (int mt = 0; mt < 2; mt++)
#pragma unroll
                    for (int nt = 0; nt < 4; nt++)
                        mma16816(acc[mt][nt], a[mt],
                                 b[nt >> 1][(nt & 1) * 2], b[nt >> 1][(nt & 1) * 2 + 1]);
            }
        }
        __syncthreads();
    }

    int rA = lane >> 2, cA = 2 * (lane & 3);
#pragma unroll
    for (int nt = 0; nt < 4; nt++) {
        int col = nbase + nt * 8 + cA;
#pragma unroll
        for (int mt = 0; mt < 2; mt++) {
            int row = mbase + mt * 16 + rA;
            *(float2*)&Csm[row * 128 + col] = make_float2(acc[mt][nt][0], acc[mt][nt][1]);
            *(float2*)&Csm[(row + 8) * 128 + col] = make_float2(acc[mt][nt][2], acc[mt][nt][3]);
        }
    }
    __syncthreads();

    int c4 = lane * 4;
    float4 bp4 = *(const float4*)(bp + c4);
    float4 gv4 = *(const float4*)(gamma + c4);
    float4 be4 = *(const float4*)(beta + c4);
    const float k1s2 = 0.70710678118654752f;
#pragma unroll
    for (int r = 0; r < 8; r++) {
        int row = wid * 8 + r;
        int grow = row0 + row;
        bool valid = (grow < Nn);
        float4 v = *(float4*)&Csm[row * 128 + c4];
        float4 xv = valid ? *(const float4*)(x + (size_t)grow * Dd + c4)
                          : make_float4(0.f, 0.f, 0.f, 0.f);
        float y[4];
        y[0] = v.x + bp4.x + xv.x; y[1] = v.y + bp4.y + xv.y;
        y[2] = v.z + bp4.z + xv.z; y[3] = v.w + bp4.w + xv.w;
        float s = 0.f, ss = 0.f;
#pragma unroll
        for (int j = 0; j < 4; j++) {
            y[j] = 0.5f * y[j] * (1.f + erff(y[j] * k1s2));
            s += y[j]; ss = fmaf(y[j], y[j], ss);
        }
#pragma unroll
        for (int o = 16; o; o >>= 1) {
            s  += __shfl_xor_sync(0xffffffffu, s, o);
            ss += __shfl_xor_sync(0xffffffffu, ss, o);
        }
        float mu = s * (1.f / 128.f);
        float var = ss * (1.f / 128.f) - mu * mu;
        float rstd = rsqrtf(fmaxf(var, 0.f) + 1e-5f);
        if (valid) {
            float4 o4;
            o4.x = (y[0] - mu) * rstd * gv4.x + be4.x;
            o4.y = (y[1] - mu) * rstd * gv4.y + be4.y;
            o4.z = (y[2] - mu) * rstd * gv4.z + be4.z;
            o4.w = (y[3] - mu) * rstd * gv4.w + be4.w;
            *(float4*)(out + (size_t)grow * Dd + c4) = o4;
        }
    }
}

// ---------------- launcher: CSR chain + cvt_wp overlapped with gemm1 --------
extern "C" void kernel_launch(void* const* d_in, const int* in_sizes, int n_in,
                              void* d_out, int out_size) {
    const float* x        = (const float*)d_in[0];
    const int*   ei       = (const int*)d_in[1];   // JAX x64 disabled -> int32
    const float* ea       = (const float*)d_in[2];
    const float* Wl       = (const float*)d_in[3];
    const float* bl       = (const float*)d_in[4];
    const float* Wr       = (const float*)d_in[5];
    const float* br       = (const float*)d_in[6];
    const float* We       = (const float*)d_in[7];
    const float* att      = (const float*)d_in[8];
    const float* bias_out = (const float*)d_in[9];
    const float* Wp       = (const float*)d_in[10];
    const float* bp       = (const float*)d_in[11];
    const float* gamma    = (const float*)d_in[12];
    const float* beta     = (const float*)d_in[13];
    float* out = (float*)d_out;

    cudaFuncSetAttribute(k_gemm1_mma, cudaFuncAttributeMaxDynamicSharedMemorySize, SMEM_G1);
    cudaFuncSetAttribute(k_gemm2_mma, cudaFuncAttributeMaxDynamicSharedMemorySize, SMEM_G2);

    static cudaStream_t s_side = 0;
    static cudaEvent_t e_fork = 0, e_join = 0;
    if (!s_side) {
        cudaStreamCreateWithFlags(&s_side, cudaStreamNonBlocking);
        cudaEventCreateWithFlags(&e_fork, cudaEventDisableTiming);
        cudaEventCreateWithFlags(&e_join, cudaEventDisableTiming);
    }

    cudaEventRecord(e_fork, 0);
    cudaStreamWaitEvent(s_side, e_fork, 0);

    // main stream: conversions + gemm1 (gemm1 = 4th launch overall for ncu)
    k_cvt_x<<<(Nn * Dd / 2 + 255) / 256, 256>>>(x);
    k_cvt_w<<<dim3(HC / 32, Dd / 32, 2), dim3(32, 8)>>>(Wl, Wr);
    k_init<<<(Nn + 255) / 256, 256, 0, s_side>>>();
    k_gemm1_mma<<<dim3((Nn + 127) / 128, 8), 256, SMEM_G1>>>(bl, br);
    // side stream: CSR build + Wp conversion (independent of gemm1)
    k_degree<<<(EPE + 255) / 256, 256, 0, s_side>>>(ei, ea);
    k_scan<<<1, 1024, 0, s_side>>>();
    k_scatter<<<(EPE + 255) / 256, 256, 0, s_side>>>(ei, ea);
    k_cvt_wp<<<(Dd * HC + 255) / 256, 256, 0, s_side>>>(Wp);
    cudaEventRecord(e_join, s_side);
    cudaStreamWaitEvent(0, e_join, 0);

    k_aggregate<<<(Nn * 32 + 255) / 256, 256>>>(We, att, bias_out);
    k_gemm2_mma<<<(Nn + 63) / 64, 256, SMEM_G2>>>(x, bp, gamma, beta, out);
}

// round 17
// speedup vs baseline: 1.0453x; 1.0453x over previous
#include <cuda_runtime.h>
#include <cuda_bf16.h>
#include <math.h>
#include <stdint.h>

#define Nn 10000
#define Ee 160000
#define EPE 170000      // E + N self loops
#define Dd 128
#define HC 512
#define ASTRIDE 136     // padded bf16 row stride for 128-wide k tiles (gemm2)
#define KSTRIDE 72      // padded bf16 row stride for 64-wide k tiles (gemm1)

typedef unsigned long long u64;

// ---- channel permutation: storage pos p <-> logical channel c -------------
// c = 128g + 16i + 4q + j ;  p = q*128 + g*32 + i*4 + j
__device__ __forceinline__ int chOf(int p) {
    int q = p >> 7, r = p & 127, g = r >> 5, w = r & 31, i = w >> 2, j = w & 3;
    return 128 * g + 16 * i + 4 * q + j;
}

// ---------------- smem helpers ----------------
__device__ __forceinline__ uint32_t saddr(const void* p) {
    return (uint32_t)__cvta_generic_to_shared(p);
}

// ---------------- cp.async helpers ----------------
__device__ __forceinline__ void cp16(uint32_t dst, const void* src) {
    asm volatile("cp.async.ca.shared.global [%0], [%1], 16;\n" :: "r"(dst), "l"(src));
}
__device__ __forceinline__ void cp16p(uint32_t dst, const void* src, bool pred) {
    int sz = pred ? 16 : 0;
    asm volatile("cp.async.ca.shared.global [%0], [%1], 16, %2;\n"
                 :: "r"(dst), "l"(src), "r"(sz));
}
__device__ __forceinline__ void cp_commit() { asm volatile("cp.async.commit_group;\n"); }
__device__ __forceinline__ void cp_wait0()  { asm volatile("cp.async.wait_group 0;\n"); }

// ---------------- packed f32x2 helpers ----------------
__device__ __forceinline__ u64 pk2(float lo, float hi) {
    u64 r; asm("mov.b64 %0, {%1, %2};" : "=l"(r) : "f"(lo), "f"(hi)); return r;
}
__device__ __forceinline__ void upk2(u64 v, float& lo, float& hi) {
    asm("mov.b64 {%0, %1}, %2;" : "=f"(lo), "=f"(hi) : "l"(v));
}
__device__ __forceinline__ void fma2(u64& d, u64 a, u64 b) {
    asm("fma.rn.f32x2 %0, %1, %2, %0;" : "+l"(d) : "l"(a), "l"(b));
}
__device__ __forceinline__ u64 add2(u64 a, u64 b) {
    u64 r; asm("add.rn.f32x2 %0, %1, %2;" : "=l"(r) : "l"(a), "l"(b)); return r;
}
__device__ __forceinline__ u64 mul2(u64 a, u64 b) {
    u64 r; asm("mul.rn.f32x2 %0, %1, %2;" : "=l"(r) : "l"(a), "l"(b)); return r;
}

// ---------------- mma.sync helpers ----------------
__device__ __forceinline__ void ldsm4(uint32_t* r, uint32_t addr) {
    asm volatile("ldmatrix.sync.aligned.m8n8.x4.shared.b16 {%0,%1,%2,%3}, [%4];"
        : "=r"(r[0]), "=r"(r[1]), "=r"(r[2]), "=r"(r[3]) : "r"(addr));
}
__device__ __forceinline__ void mma16816(float* c, const uint32_t* a, uint32_t b0, uint32_t b1) {
    asm volatile(
        "mma.sync.aligned.m16n8k16.row.col.f32.bf16.bf16.f32 "
        "{%0,%1,%2,%3}, {%4,%5,%6,%7}, {%8,%9}, {%0,%1,%2,%3};"
        : "+f"(c[0]), "+f"(c[1]), "+f"(c[2]), "+f"(c[3])
        : "r"(a[0]), "r"(a[1]), "r"(a[2]), "r"(a[3]), "r"(b0), "r"(b1));
}

// ---------------- device scratch ----------------
__device__ float g_xl[Nn * HC];                 // PERMUTED columns
__device__ float g_xr[Nn * HC];                 // PERMUTED columns
__device__ __nv_bfloat16 g_agghi[Nn * HC];      // PERMUTED columns
__device__ __nv_bfloat16 g_agglo[Nn * HC];
__device__ int   g_deg[Nn];
__device__ int   g_off[Nn + 1];
__device__ int   g_cur[Nn];
__device__ int   g_esrc[EPE];
__device__ float g_eav[EPE];
__device__ float g_easum;
__device__ __nv_bfloat16 g_xhi[Nn * Dd];
__device__ __nv_bfloat16 g_xlo[Nn * Dd];
__device__ __nv_bfloat16 g_wthi[2 * HC * Dd];   // [mat][n][k] = W[k][n]
__device__ __nv_bfloat16 g_wtlo[2 * HC * Dd];
__device__ __nv_bfloat16 g_wphi[Dd * HC];       // [n=128][k_perm=512]
__device__ __nv_bfloat16 g_wplo[Dd * HC];

// ---------------- init ----------------
__global__ void k_init() {
    int i = blockIdx.x * blockDim.x + threadIdx.x;
    if (i < Nn) { g_deg[i] = 0; g_cur[i] = 0; }
    if (i == 0) g_easum = 0.f;
}

// ---------------- convert x -> bf16 hi/lo ----------------
__global__ void k_cvt_x(const float* __restrict__ x) {
    int i = blockIdx.x * 256 + threadIdx.x;
    if (i >= Nn * Dd / 2) return;
    float2 v = ((const float2*)x)[i];
    __nv_bfloat16 h0 = __float2bfloat16(v.x), h1 = __float2bfloat16(v.y);
    __nv_bfloat16 l0 = __float2bfloat16(v.x - __bfloat162float(h0));
    __nv_bfloat16 l1 = __float2bfloat16(v.y - __bfloat162float(h1));
    ((__nv_bfloat162*)g_xhi)[i] = __halves2bfloat162(h0, h1);
    ((__nv_bfloat162*)g_xlo)[i] = __halves2bfloat162(l0, l1);
}

// ---------------- transpose+convert Wl/Wr -> [n][k] bf16 hi/lo -------------
__global__ void k_cvt_w(const float* __restrict__ Wl, const float* __restrict__ Wr) {
    __shared__ float t[32][33];
    int m = blockIdx.z;
    const float* W = m ? Wr : Wl;
    int nb = blockIdx.x * 32, kb = blockIdx.y * 32;
    int tx = threadIdx.x, ty = threadIdx.y;
#pragma unroll
    for (int j = 0; j < 4; j++)
        t[ty + 8 * j][tx] = W[(kb + ty + 8 * j) * HC + nb + tx];
    __syncthreads();
#pragma unroll
    for (int j = 0; j < 4; j++) {
        float v = t[tx][ty + 8 * j];
        __nv_bfloat16 h = __float2bfloat16(v);
        __nv_bfloat16 l = __float2bfloat16(v - __bfloat162float(h));
        int o = m * HC * Dd + (nb + ty + 8 * j) * Dd + kb + tx;
        g_wthi[o] = h;
        g_wtlo[o] = l;
    }
}

// ---------------- Wp -> [n][k_perm] bf16 hi/lo (gather permutation) --------
__global__ void k_cvt_wp(const float* __restrict__ Wp) {
    int idx = blockIdx.x * 256 + threadIdx.x;
    if (idx >= Dd * HC) return;
    int n = idx >> 9, p = idx & 511;
    float v = Wp[(size_t)chOf(p) * Dd + n];
    __nv_bfloat16 h = __float2bfloat16(v);
    __nv_bfloat16 l = __float2bfloat16(v - __bfloat162float(h));
    g_wphi[(size_t)n * HC + p] = h;
    g_wplo[(size_t)n * HC + p] = l;
}

// ---------------- GEMM1: mma.sync bf16, 2x64-k stages, cp.async prefetch ---
// Full 254 regs / 1 CTA per SM (no spills); stage-1 fill hidden by cp.async.
#define G1STAGE (4 * 128 * KSTRIDE)        // bf16 elems per stage (4 arrays)
#define SMEM_G1 (2 * G1STAGE * 2)          // 147456 B ; Csm 128*132*4 fits
#define CSTRIDE 132

__global__ __launch_bounds__(256) void k_gemm1_mma(const float* __restrict__ bl,
                                                   const float* __restrict__ br) {
    extern __shared__ __nv_bfloat16 smb[];
    float* Csm = (float*)smb;                    // reused after compute

    int tid = threadIdx.x, wid = tid >> 5, lane = tid & 31;
    int cb = blockIdx.y;
    int mat = cb >> 2, g = cb & 3, colbase = g * 128;
    const float* bias = mat ? br : bl;
    float* out = mat ? g_xr : g_xl;
    int row0 = blockIdx.x * 128;

    const __nv_bfloat16* gbh = g_wthi + (size_t)mat * HC * Dd + (size_t)colbase * Dd;
    const __nv_bfloat16* gbl = g_wtlo + (size_t)mat * HC * Dd + (size_t)colbase * Dd;

    auto cpfill = [&](int k0, int s) {
        __nv_bfloat16* Ah = smb + s * G1STAGE;
        __nv_bfloat16* Al = Ah + 128 * KSTRIDE;
        __nv_bfloat16* Bh = Al + 128 * KSTRIDE;
        __nv_bfloat16* Bl = Bh + 128 * KSTRIDE;
#pragma unroll
        for (int i = 0; i < 4; i++) {
            int idx = tid + i * 256;
            int row = idx >> 3, ch = idx & 7;
            int grow = row0 + row;
            bool ok = (grow < Nn);
            int srow = ok ? grow : 0;        // keep src valid; sz=0 zero-fills
            cp16p(saddr(Ah + row * KSTRIDE + ch * 8), g_xhi + (size_t)srow * Dd + k0 + ch * 8, ok);
            cp16p(saddr(Al + row * KSTRIDE + ch * 8), g_xlo + (size_t)srow * Dd + k0 + ch * 8, ok);
            cp16(saddr(Bh + row * KSTRIDE + ch * 8), gbh + (size_t)row * Dd + k0 + ch * 8);
            cp16(saddr(Bl + row * KSTRIDE + ch * 8), gbl + (size_t)row * Dd + k0 + ch * 8);
        }
    };

    float acc[4][4][4];
#pragma unroll
    for (int mt = 0; mt < 4; mt++)
#pragma unroll
        for (int nt = 0; nt < 4; nt++)
#pragma unroll
            for (int j = 0; j < 4; j++) acc[mt][nt][j] = 0.f;

    int warpM = wid & 1, warpN = wid >> 1;
    int mbase = warpM * 64, nbase = warpN * 32;
    int t8 = lane >> 3, r8 = lane & 7;
    int aRow = (t8 & 1) * 8 + r8, aK = (t8 >> 1) * 8;
    int bN = (t8 >> 1) * 8 + r8, bK = (t8 & 1) * 8;

    cpfill(0, 0); cp_commit();
    cp_wait0(); __syncthreads();
    cpfill(64, 1); cp_commit();            // prefetch stage 1 under stage-0 compute

#pragma unroll 1
    for (int stage = 0; stage < 2; stage++) {
        const __nv_bfloat16* base = smb + stage * G1STAGE;
        const __nv_bfloat16* Ah = base;
        const __nv_bfloat16* Al = Ah + 128 * KSTRIDE;
        const __nv_bfloat16* Bh = Al + 128 * KSTRIDE;
        const __nv_bfloat16* Bl = Bh + 128 * KSTRIDE;
#pragma unroll
        for (int term = 0; term < 3; term++) {
            const __nv_bfloat16* Asm = (term == 2) ? Al : Ah;
            const __nv_bfloat16* Bsm = (term == 1) ? Bl : Bh;
#pragma unroll
            for (int ks = 0; ks < 4; ks++) {
                uint32_t a[4][4], b[2][4];
#pragma unroll
                for (int mt = 0; mt < 4; mt++)
                    ldsm4(a[mt], saddr(Asm + (mbase + mt * 16 + aRow) * KSTRIDE + ks * 16 + aK));
#pragma unroll
                for (int gg = 0; gg < 2; gg++)
                    ldsm4(b[gg], saddr(Bsm + (nbase + gg * 16 + bN) * KSTRIDE + ks * 16 + bK));
#pragma unroll
                for (int mt = 0; mt < 4; mt++)
#pragma unroll
                    for (int nt = 0; nt < 4; nt++)
                        mma16816(acc[mt][nt], a[mt],
                                 b[nt >> 1][(nt & 1) * 2], b[nt >> 1][(nt & 1) * 2 + 1]);
            }
        }
        if (stage == 0) { cp_wait0(); __syncthreads(); }
    }
    __syncthreads();   // all warps done reading smem; reuse as Csm

    // stage C (+bias) into smem in LOCAL permuted order
    int rA = lane >> 2, cA = 2 * (lane & 3);
#pragma unroll
    for (int nt = 0; nt < 4; nt++) {
        int c = nbase + nt * 8 + cA;
        float2 bv = *(const float2*)(bias + colbase + c);
        int ploc = ((c & 15) >> 2) * 32 + (c >> 4) * 4 + (c & 3);
#pragma unroll
        for (int mt = 0; mt < 4; mt++) {
            int row = mbase + mt * 16 + rA;
            *(float2*)&Csm[row * CSTRIDE + ploc] =
                make_float2(acc[mt][nt][0] + bv.x, acc[mt][nt][1] + bv.y);
            *(float2*)&Csm[(row + 8) * CSTRIDE + ploc] =
                make_float2(acc[mt][nt][2] + bv.x, acc[mt][nt][3] + bv.y);
        }
    }
    __syncthreads();

    // coalesced permuted global stores: ploc = q*32 + w -> p = q*128 + g*32 + w
#pragma unroll
    for (int it = 0; it < 16; it++) {
        int idx = tid + it * 256;
        int row = idx >> 5, t = idx & 31;
        int grow = row0 + row;
        if (grow < Nn) {
            float4 v = *(float4*)&Csm[row * CSTRIDE + t * 4];
            int p = (t >> 3) * 128 + g * 32 + (t & 7) * 4;
            *(float4*)(out + (size_t)grow * HC + p) = v;
        }
    }
}

// ---------------- degree histogram + edge_attr sum (fused) ----------------
__global__ void k_degree(const int* __restrict__ ei, const float* __restrict__ ea) {
    __shared__ float sh[8];
    int e = blockIdx.x * blockDim.x + threadIdx.x;
    float v = 0.f;
    if (e < EPE) {
        int dst = (e < Ee) ? ei[Ee + e] : (e - Ee);
        atomicAdd(&g_deg[dst], 1);
        if (e < Ee) v = ea[e];
    }
#pragma unroll
    for (int o = 16; o; o >>= 1) v += __shfl_xor_sync(0xffffffffu, v, o);
    if ((threadIdx.x & 31) == 0) sh[threadIdx.x >> 5] = v;
    __syncthreads();
    if (threadIdx.x == 0) {
        float s = 0.f;
#pragma unroll
        for (int w = 0; w < 8; w++) s += sh[w];
        atomicAdd(&g_easum, s);
    }
}

// ---------------- exclusive scan over N (single block) ----------------
__global__ void k_scan() {
    __shared__ int sb[1024];
    int t = threadIdx.x;
    const int CH = 10;
    int lo = t * CH;
    int s = 0;
    for (int i = 0; i < CH; i++) { int idx = lo + i; if (idx < Nn) s += g_deg[idx]; }
    sb[t] = s;
    __syncthreads();
    for (int o = 1; o < 1024; o <<= 1) {
        int v = (t >= o) ? sb[t - o] : 0;
        __syncthreads();
        sb[t] += v;
        __syncthreads();
    }
    int run = sb[t] - s;
    for (int i = 0; i < CH; i++) {
        int idx = lo + i;
        if (idx < Nn) { g_off[idx] = run; run += g_deg[idx]; }
    }
    if (t == 1023) g_off[Nn] = sb[1023];
}

// ---------------- scatter edges into CSR by dst ----------------
__global__ void k_scatter(const int* __restrict__ ei, const float* __restrict__ ea) {
    int e = blockIdx.x * blockDim.x + threadIdx.x;
    if (e >= EPE) return;
    int src, dst; float a;
    if (e < Ee) { src = ei[e]; dst = ei[Ee + e]; a = ea[e]; }
    else        { src = e - Ee; dst = src; a = g_easum * (1.0f / Ee); }
    int pos = atomicAdd(&g_cur[dst], 1);
    int idx = g_off[dst] + pos;
    g_esrc[idx] = src;
    g_eav[idx]  = a;
}

// ---------------- warp-per-node aggregation, packed f32x2 math -------------
// leaky(z) = max(z, 0.2z) = 0.6z + 0.4|z|  (exact to ulp, branch-free packed)
__global__ __launch_bounds__(256) void k_aggregate(const float* __restrict__ We,
        const float* __restrict__ att, const float* __restrict__ bias_out) {
    __shared__ float s_we[HC], s_at[HC];
    for (int p = threadIdx.x; p < HC; p += 256) {
        int ch = chOf(p);
        s_we[p] = We[ch];
        s_at[p] = att[ch];
    }
    __syncthreads();

    int gw = (blockIdx.x * 256 + threadIdx.x) >> 5;
    if (gw >= Nn) return;
    int lane = threadIdx.x & 31;
    int co = lane * 4;
    int g = lane >> 3, i = lane & 7;

    const u64 MASK = 0x7FFFFFFF7FFFFFFFull;
    const u64 C04 = pk2(0.4f, 0.4f), C06 = pk2(0.6f, 0.6f);

    u64 xr2[8], we2[8], at2[8], acc2[8];
#pragma unroll
    for (int q = 0; q < 4; q++) {
        float4 v = *(const float4*)(g_xr + (size_t)gw * HC + q * 128 + co);
        xr2[q*2] = pk2(v.x, v.y); xr2[q*2+1] = pk2(v.z, v.w);
        float4 w4 = *(const float4*)&s_we[q * 128 + co];
        we2[q*2] = pk2(w4.x, w4.y); we2[q*2+1] = pk2(w4.z, w4.w);
        float4 a4 = *(const float4*)&s_at[q * 128 + co];
        at2[q*2] = pk2(a4.x, a4.y); at2[q*2+1] = pk2(a4.z, a4.w);
    }
#pragma unroll
    for (int k = 0; k < 8; k++) acc2[k] = 0ull;

    float ssum = 0.f;
    int e0 = g_off[gw], e1 = g_off[gw + 1];

    u64 bufA[8], bufB[8];
    auto ldxv = [&](u64* d, int s) {
#pragma unroll
        for (int q = 0; q < 4; q++) {
            ulonglong2 v = *(const ulonglong2*)(g_xl + (size_t)s * HC + q * 128 + co);
            d[q*2] = v.x; d[q*2+1] = v.y;
        }
    };
    auto process = [&](const u64* xv, float a) {
        u64 a2 = pk2(a, a);
        u64 pp = 0ull;
#pragma unroll
        for (int k = 0; k < 8; k++) {
            u64 t = xr2[k];
            fma2(t, a2, we2[k]);          // t = xr + a*we
            u64 z = add2(t, xv[k]);       // z = xv + xr + a*we
            u64 r = mul2(z & MASK, C04);  // 0.4|z|
            fma2(r, z, C06);              // 0.6z + 0.4|z| = leaky(z)
            fma2(pp, r, at2[k]);          // dot with att
        }
        float plo, phi;
        upk2(pp, plo, phi);
        float p = plo + phi;
        p += __shfl_xor_sync(0xffffffffu, p, 1);
        p += __shfl_xor_sync(0xffffffffu, p, 2);
        p += __shfl_xor_sync(0xffffffffu, p, 4);
        float w = __expf(p);
        ssum += w;
        u64 w2 = pk2(w, w);
#pragma unroll
        for (int k = 0; k < 8; k++) fma2(acc2[k], w2, xv[k]);
    };

    if (e0 < e1) {
        ldxv(bufA, g_esrc[e0]);
        int e = e0;
        for (; e + 2 <= e1; e += 2) {
            ldxv(bufB, g_esrc[e + 1]);
            process(bufA, g_eav[e]);
            if (e + 2 < e1) ldxv(bufA, g_esrc[e + 2]);
            process(bufB, g_eav[e + 1]);
        }
        if (e < e1) process(bufA, g_eav[e]);
    }

    float inv = 1.f / (ssum + 1e-16f);
#pragma unroll
    for (int q = 0; q < 4; q++) {
        float4 bo = *(const float4*)(bias_out + g * 128 + i * 16 + q * 4);
        float a0, a1, a2v, a3;
        upk2(acc2[q*2], a0, a1);
        upk2(acc2[q*2+1], a2v, a3);
        float v0 = fmaf(a0, inv, bo.x);
        float v1 = fmaf(a1, inv, bo.y);
        float v2 = fmaf(a2v, inv, bo.z);
        float v3 = fmaf(a3, inv, bo.w);
        __nv_bfloat16 h0 = __float2bfloat16(v0), h1 = __float2bfloat16(v1);
        __nv_bfloat16 h2 = __float2bfloat16(v2), h3 = __float2bfloat16(v3);
        __nv_bfloat16 l0 = __float2bfloat16(v0 - __bfloat162float(h0));
        __nv_bfloat16 l1 = __float2bfloat16(v1 - __bfloat162float(h1));
        __nv_bfloat16 l2 = __float2bfloat16(v2 - __bfloat162float(h2));
        __nv_bfloat16 l3 = __float2bfloat16(v3 - __bfloat162float(h3));
        size_t o = (size_t)gw * HC + q * 128 + co;
        *(__nv_bfloat162*)(g_agghi + o)     = __halves2bfloat162(h0, h1);
        *(__nv_bfloat162*)(g_agghi + o + 2) = __halves2bfloat162(h2, h3);
        *(__nv_bfloat162*)(g_agglo + o)     = __halves2bfloat162(l0, l1);
        *(__nv_bfloat162*)(g_agglo + o + 2) = __halves2bfloat162(l2, l3);
    }
}

// ---------------- GEMM2 via mma.sync + GELU/LN epilogue ---------------------
#define SMEM_G2 ((64 * ASTRIDE * 2 + 128 * ASTRIDE * 2) * 2)   // 104448 B

__global__ __launch_bounds__(256) void k_gemm2_mma(const float* __restrict__ x,
        const float* __restrict__ bp, const float* __restrict__ gamma,
        const float* __restrict__ beta, float* __restrict__ out) {
    extern __shared__ __nv_bfloat16 smb2[];
    __nv_bfloat16* Ah = smb2;
    __nv_bfloat16* Al = Ah + 64 * ASTRIDE;
    __nv_bfloat16* Bh = Al + 64 * ASTRIDE;
    __nv_bfloat16* Bl = Bh + 128 * ASTRIDE;
    float* Csm = (float*)smb2;

    int tid = threadIdx.x, wid = tid >> 5, lane = tid & 31;
    int row0 = blockIdx.x * 64;

    float acc[2][4][4];
#pragma unroll
    for (int mt = 0; mt < 2; mt++)
#pragma unroll
        for (int nt = 0; nt < 4; nt++)
#pragma unroll
            for (int j = 0; j < 4; j++) acc[mt][nt][j] = 0.f;

    int warpM = wid & 1, warpN = wid >> 1;
    int mbase = warpM * 32, nbase = warpN * 32;
    int t8 = lane >> 3, r8 = lane & 7;
    int aRow = (t8 & 1) * 8 + r8, aK = (t8 >> 1) * 8;
    int bN = (t8 >> 1) * 8 + r8, bK = (t8 & 1) * 8;

#pragma unroll 1
    for (int stage = 0; stage < 4; stage++) {
        int k0 = stage * 128;
#pragma unroll
        for (int i = 0; i < 4; i++) {
            int idx = tid + i * 256;
            int row = idx >> 4, ch = idx & 15;
            int grow = row0 + row;
            uint4 vh = make_uint4(0, 0, 0, 0), vl = make_uint4(0, 0, 0, 0);
            if (grow < Nn) {
                vh = *(const uint4*)(g_agghi + (size_t)grow * HC + k0 + ch * 8);
                vl = *(const uint4*)(g_agglo + (size_t)grow * HC + k0 + ch * 8);
            }
            *(uint4*)(Ah + row * ASTRIDE + ch * 8) = vh;
            *(uint4*)(Al + row * ASTRIDE + ch * 8) = vl;
        }
#pragma unroll
        for (int i = 0; i < 8; i++) {
            int idx = tid + i * 256;
            int row = idx >> 4, ch = idx & 15;
            *(uint4*)(Bh + row * ASTRIDE + ch * 8) =
                *(const uint4*)(g_wphi + (size_t)row * HC + k0 + ch * 8);
            *(uint4*)(Bl + row * ASTRIDE + ch * 8) =
                *(const uint4*)(g_wplo + (size_t)row * HC + k0 + ch * 8);
        }
        __syncthreads();

#pragma unroll
        for (int term = 0; term < 3; term++) {
            const __nv_bfloat16* Asm = (term == 2) ? Al : Ah;
            const __nv_bfloat16* Bsm = (term == 1) ? Bl : Bh;
#pragma unroll
            for (int ks = 0; ks < 8; ks++) {
                uint32_t a[2][4], b[2][4];
#pragma unroll
                for (int mt = 0; mt < 2; mt++)
                    ldsm4(a[mt], saddr(Asm + (mbase + mt * 16 + aRow) * ASTRIDE + ks * 16 + aK));
#pragma unroll
                for (int gg = 0; gg < 2; gg++)
                    ldsm4(b[gg], saddr(Bsm + (nbase + gg * 16 + bN) * ASTRIDE + ks * 16 + bK));
#pragma unroll
                for (int mt = 0; mt < 2; mt++)
#pragma unroll
                    for (int nt = 0; nt < 4; nt++)
                        mma16816(acc[mt][nt], a[mt],
                                 b[nt >> 1][(nt & 1) * 2], b[nt >> 1][(nt & 1) * 2 + 1]);
            }
        }
        __syncthreads();
    }

    int rA = lane >> 2, cA = 2 * (lane & 3);
#pragma unroll
    for (int nt = 0; nt < 4; nt++) {
        int col = nbase + nt * 8 + cA;
#pragma unroll
        for (int mt = 0; mt < 2; mt++) {
            int row = mbase + mt * 16 + rA;
            *(float2*)&Csm[row * 128 + col] = make_float2(acc[mt][nt][0], acc[mt][nt][1]);
            *(float2*)&Csm[(row + 8) * 128 + col] = make_float2(acc[mt][nt][2], acc[mt][nt][3]);
        }
    }
    __syncthreads();

    int c4 = lane * 4;
    float4 bp4 = *(const float4*)(bp + c4);
    float4 gv4 = *(const float4*)(gamma + c4);
    float4 be4 = *(const float4*)(beta + c4);
    const float k1s2 = 0.70710678118654752f;
#pragma unroll
    for (int r = 0; r < 8; r++) {
        int row = wid * 8 + r;
        int grow = row0 + row;
        bool valid = (grow < Nn);
        float4 v = *(float4*)&Csm[row * 128 + c4];
        float4 xv = valid ? *(const float4*)(x + (size_t)grow * Dd + c4)
                          : make_float4(0.f, 0.f, 0.f, 0.f);
        float y[4];
        y[0] = v.x + bp4.x + xv.x; y[1] = v.y + bp4.y + xv.y;
        y[2] = v.z + bp4.z + xv.z; y[3] = v.w + bp4.w + xv.w;
        float s = 0.f, ss = 0.f;
#pragma unroll
        for (int j = 0; j < 4; j++) {
            y[j] = 0.5f * y[j] * (1.f + erff(y[j] * k1s2));
            s += y[j]; ss = fmaf(y[j], y[j], ss);
        }
#pragma unroll
        for (int o = 16; o; o >>= 1) {
            s  += __shfl_xor_sync(0xffffffffu, s, o);
            ss += __shfl_xor_sync(0xffffffffu, ss, o);
        }
        float mu = s * (1.f / 128.f);
        float var = ss * (1.f / 128.f) - mu * mu;
        float rstd = rsqrtf(fmaxf(var, 0.f) + 1e-5f);
        if (valid) {
            float4 o4;
            o4.x = (y[0] - mu) * rstd * gv4.x + be4.x;
            o4.y = (y[1] - mu) * rstd * gv4.y + be4.y;
            o4.z = (y[2] - mu) * rstd * gv4.z + be4.z;
            o4.w = (y[3] - mu) * rstd * gv4.w + be4.w;
            *(float4*)(out + (size_t)grow * Dd + c4) = o4;
        }
    }
}

// ---------------- launcher: CSR chain + cvt_wp overlapped with gemm1 --------
extern "C" void kernel_launch(void* const* d_in, const int* in_sizes, int n_in,
                              void* d_out, int out_size) {
    const float* x        = (const float*)d_in[0];
    const int*   ei       = (const int*)d_in[1];   // JAX x64 disabled -> int32
    const float* ea       = (const float*)d_in[2];
    const float* Wl       = (const float*)d_in[3];
    const float* bl       = (const float*)d_in[4];
    const float* Wr       = (const float*)d_in[5];
    const float* br       = (const float*)d_in[6];
    const float* We       = (const float*)d_in[7];
    const float* att      = (const float*)d_in[8];
    const float* bias_out = (const float*)d_in[9];
    const float* Wp       = (const float*)d_in[10];
    const float* bp       = (const float*)d_in[11];
    const float* gamma    = (const float*)d_in[12];
    const float* beta     = (const float*)d_in[13];
    float* out = (float*)d_out;

    cudaFuncSetAttribute(k_gemm1_mma, cudaFuncAttributeMaxDynamicSharedMemorySize, SMEM_G1);
    cudaFuncSetAttribute(k_gemm2_mma, cudaFuncAttributeMaxDynamicSharedMemorySize, SMEM_G2);

    static cudaStream_t s_side = 0;
    static cudaEvent_t e_fork = 0, e_join = 0;
    if (!s_side) {
        cudaStreamCreateWithFlags(&s_side, cudaStreamNonBlocking);
        cudaEventCreateWithFlags(&e_fork, cudaEventDisableTiming);
        cudaEventCreateWithFlags(&e_join, cudaEventDisableTiming);
    }

    cudaEventRecord(e_fork, 0);
    cudaStreamWaitEvent(s_side, e_fork, 0);

    // main stream: conversions + gemm1 (gemm1 = 4th launch overall for ncu)
    k_cvt_x<<<(Nn * Dd / 2 + 255) / 256, 256>>>(x);
    k_cvt_w<<<dim3(HC / 32, Dd / 32, 2), dim3(32, 8)>>>(Wl, Wr);
    k_init<<<(Nn + 255) / 256, 256, 0, s_side>>>();
    k_gemm1_mma<<<dim3((Nn + 127) / 128, 8), 256, SMEM_G1>>>(bl, br);
    // side stream: CSR build + Wp conversion (independent of gemm1)
    k_degree<<<(EPE + 255) / 256, 256, 0, s_side>>>(ei, ea);
    k_scan<<<1, 1024, 0, s_side>>>();
    k_scatter<<<(EPE + 255) / 256, 256, 0, s_side>>>(ei, ea);
    k_cvt_wp<<<(Dd * HC + 255) / 256, 256, 0, s_side>>>(Wp);
    cudaEventRecord(e_join, s_side);
    cudaStreamWaitEvent(0, e_join, 0);

    k_aggregate<<<(Nn * 32 + 255) / 256, 256>>>(We, att, bias_out);
    k_gemm2_mma<<<(Nn + 63) / 64, 256, SMEM_G2>>>(x, bp, gamma, beta, out);
}